// round 1
// baseline (speedup 1.0000x reference)
#include <cuda_runtime.h>
#include <stdint.h>

#define BATCH    16
#define NBOX     4096
#define NCLS     80
#define MAX_DET  100
#define IOU_THR  0.5f
#define CONF_THR 0.5f

// scratch: per-row sort keys  (score_bits << 32) | (0xFFFFFFFF - idx)
__device__ unsigned long long g_keys[BATCH * NBOX];

// ---------------------------------------------------------------------------
// Kernel 1: softmax(square(x*10)) per row, write cls_predictions, emit keys.
// One warp per row of 80. MUFU(EX2)-bound.
// ---------------------------------------------------------------------------
__global__ void __launch_bounds__(256)
softmax_key_kernel(const float* __restrict__ cls_in,
                   float* __restrict__ cls_out,
                   unsigned long long* __restrict__ keys)
{
    const int lane = threadIdx.x & 31;
    const int row  = blockIdx.x * (blockDim.x >> 5) + (threadIdx.x >> 5);
    if (row >= BATCH * NBOX) return;

    const float* in = cls_in + (size_t)row * NCLS;

    // lanes cover cols: lane, lane+32, lane+64(<80 for lane<16)
    const bool has2 = lane < (NCLS - 64);
    float x0 = in[lane]      * 10.0f;
    float x1 = in[lane + 32] * 10.0f;
    float x2 = has2 ? in[lane + 64] * 10.0f : 0.0f;
    float a0 = x0 * x0, a1 = x1 * x1, a2 = x2 * x2;

    float amax = fmaxf(a0, a1);
    if (has2) amax = fmaxf(amax, a2);
    #pragma unroll
    for (int o = 16; o; o >>= 1)
        amax = fmaxf(amax, __shfl_xor_sync(0xffffffffu, amax, o));

    float e0 = expf(a0 - amax);
    float e1 = expf(a1 - amax);
    float e2 = has2 ? expf(a2 - amax) : 0.0f;

    float s = e0 + e1 + e2;
    #pragma unroll
    for (int o = 16; o; o >>= 1)
        s += __shfl_xor_sync(0xffffffffu, s, o);

    const float recip = 1.0f / s;   // IEEE divide, once per row
    float o0 = e0 * recip, o1 = e1 * recip, o2 = e2 * recip;

    float* out = cls_out + (size_t)row * NCLS;
    out[lane]      = o0;
    out[lane + 32] = o1;
    if (has2) out[lane + 64] = o2;

    float m = fmaxf(o0, o1);
    if (has2) m = fmaxf(m, o2);
    #pragma unroll
    for (int o = 16; o; o >>= 1)
        m = fmaxf(m, __shfl_xor_sync(0xffffffffu, m, o));

    if (lane == 0) {
        const unsigned n = (unsigned)(row & (NBOX - 1));
        keys[row] = ((unsigned long long)__float_as_uint(m) << 32)
                  | (unsigned long long)(0xffffffffu - n);
    }
}

// ---------------------------------------------------------------------------
// Kernel 2: per-batch descending bitonic sort of 4096 u64 keys in smem,
// then warp-0 greedy NMS with early exit at MAX_DET kept, then output write.
// ---------------------------------------------------------------------------
__global__ void __launch_bounds__(1024)
nms_kernel(const float* __restrict__ boxes,        // [B,N,4]
           const float* __restrict__ cls_soft,     // [B,N,C] (written by k1)
           const unsigned long long* __restrict__ keys,
           float* __restrict__ nms_box,            // [B,MAX_DET,4]
           float* __restrict__ nms_cls)            // [B,MAX_DET,C]
{
    __shared__ unsigned long long sk[NBOX];
    __shared__ float ky1[MAX_DET], kx1[MAX_DET], ky2[MAX_DET], kx2[MAX_DET], kar[MAX_DET];
    __shared__ int   kidx[MAX_DET];
    __shared__ int   s_count;

    const int b   = blockIdx.x;
    const int tid = threadIdx.x;

    for (int i = tid; i < NBOX; i += blockDim.x)
        sk[i] = keys[b * NBOX + i];
    __syncthreads();

    // ---- bitonic sort, descending (keys unique: idx embedded) ----
    for (int k = 2; k <= NBOX; k <<= 1) {
        for (int j = k >> 1; j > 0; j >>= 1) {
            for (int p = tid; p < NBOX / 2; p += blockDim.x) {
                int i = ((p & ~(j - 1)) << 1) | (p & (j - 1));
                int l = i | j;
                unsigned long long a = sk[i], c = sk[l];
                bool sw = ((i & k) == 0) ? (a < c) : (a > c);
                if (sw) { sk[i] = c; sk[l] = a; }
            }
            __syncthreads();
        }
    }

    // ---- greedy NMS (warp 0), early exit at MAX_DET kept or score<=thr ----
    if (tid < 32) {
        int count = 0;
        const float* bb = boxes + (size_t)b * NBOX * 4;
        for (int r = 0; r < NBOX && count < MAX_DET; r++) {
            const unsigned long long key = sk[r];
            const float score = __uint_as_float((unsigned)(key >> 32));
            if (!(score > CONF_THR)) break;          // sorted: all rest invalid
            const int idx = (int)(0xffffffffu - (unsigned)(key & 0xffffffffu));

            const float b0 = bb[idx * 4 + 0], b1 = bb[idx * 4 + 1];
            const float b2 = bb[idx * 4 + 2], b3 = bb[idx * 4 + 3];
            const float y1 = fminf(b0, b2), y2 = fmaxf(b0, b2);
            const float x1 = fminf(b1, b3), x2 = fmaxf(b1, b3);
            const float area = (y2 - y1) * (x2 - x1);

            bool sup = false;
            for (int j = tid; j < count; j += 32) {
                float ih = fmaxf(0.0f, fminf(y2, ky2[j]) - fmaxf(y1, ky1[j]));
                float iw = fmaxf(0.0f, fminf(x2, kx2[j]) - fmaxf(x1, kx1[j]));
                float inter = ih * iw;
                float uni   = area + kar[j] - inter;
                float iou   = (inter > 0.0f) ? inter / uni : 0.0f;
                if (iou > IOU_THR) { sup = true; break; }
            }
            if (__ballot_sync(0xffffffffu, sup) == 0u) {   // keep
                if (tid == 0) {
                    ky1[count] = y1; kx1[count] = x1;
                    ky2[count] = y2; kx2[count] = x2;
                    kar[count] = area; kidx[count] = idx;
                }
                count++;
                __syncwarp();
            }
        }
        if (tid == 0) s_count = count;
    }
    __syncthreads();
    const int count = s_count;

    // ---- outputs (zero-pad beyond count; d_out is poisoned) ----
    float* ob = nms_box + (size_t)b * MAX_DET * 4;
    for (int t = tid; t < MAX_DET * 4; t += blockDim.x) {
        int k = t >> 2, c = t & 3;
        ob[t] = (k < count)
              ? boxes[(size_t)b * NBOX * 4 + (size_t)kidx[k] * 4 + c]
              : 0.0f;
    }
    float* oc = nms_cls + (size_t)b * MAX_DET * NCLS;
    for (int t = tid; t < MAX_DET * NCLS; t += blockDim.x) {
        int k = t / NCLS, c = t % NCLS;
        oc[t] = (k < count)
              ? cls_soft[((size_t)b * NBOX + (size_t)kidx[k]) * NCLS + c]
              : 0.0f;
    }
}

// ---------------------------------------------------------------------------
extern "C" void kernel_launch(void* const* d_in, const int* in_sizes, int n_in,
                              void* d_out, int out_size)
{
    // inputs: box_prediction [16,4096,4] (=262144 elems), class_prediction
    // [16,4096,80] (=5242880 elems). Disambiguate by size defensively.
    const float* boxes;
    const float* cls;
    if (in_sizes[0] == BATCH * NBOX * 4) {
        boxes = (const float*)d_in[0];
        cls   = (const float*)d_in[1];
    } else {
        boxes = (const float*)d_in[1];
        cls   = (const float*)d_in[0];
    }

    float* out      = (float*)d_out;
    float* nms_box  = out;                                  // [16,100,4]
    float* nms_cls  = out + BATCH * MAX_DET * 4;            // [16,100,80]
    float* cls_pred = out + BATCH * MAX_DET * 4
                          + BATCH * MAX_DET * NCLS;         // [16,4096,80]

    unsigned long long* keys = nullptr;
    cudaGetSymbolAddress((void**)&keys, g_keys);

    const int rows = BATCH * NBOX;                 // 65536
    softmax_key_kernel<<<rows / 8, 256>>>(cls, cls_pred, keys);
    nms_kernel<<<BATCH, 1024>>>(boxes, cls_pred, keys, nms_box, nms_cls);
}

// round 2
// speedup vs baseline: 1.3979x; 1.3979x over previous
#include <cuda_runtime.h>
#include <stdint.h>

#define BATCH    16
#define NBOX     4096
#define NCLS     80
#define MAX_DET  100
#define IOU_THR  0.5f
#define CONF_THR 0.5f

// scratch: per-row sort keys  (score_bits << 32) | (0xFFFFFFFF - idx)
__device__ unsigned long long g_keys[BATCH * NBOX];

// ---------------------------------------------------------------------------
// Kernel 1: softmax(square(x*10)) per row, write cls_predictions, emit keys.
// One warp per row of 80.
// ---------------------------------------------------------------------------
__global__ void __launch_bounds__(256)
softmax_key_kernel(const float* __restrict__ cls_in,
                   float* __restrict__ cls_out,
                   unsigned long long* __restrict__ keys)
{
    const int lane = threadIdx.x & 31;
    const int row  = blockIdx.x * (blockDim.x >> 5) + (threadIdx.x >> 5);
    if (row >= BATCH * NBOX) return;

    const float* in = cls_in + (size_t)row * NCLS;

    const bool has2 = lane < (NCLS - 64);
    float x0 = in[lane]      * 10.0f;
    float x1 = in[lane + 32] * 10.0f;
    float x2 = has2 ? in[lane + 64] * 10.0f : 0.0f;
    float a0 = x0 * x0, a1 = x1 * x1, a2 = x2 * x2;

    float amax = fmaxf(a0, a1);
    if (has2) amax = fmaxf(amax, a2);
    #pragma unroll
    for (int o = 16; o; o >>= 1)
        amax = fmaxf(amax, __shfl_xor_sync(0xffffffffu, amax, o));

    float e0 = expf(a0 - amax);
    float e1 = expf(a1 - amax);
    float e2 = has2 ? expf(a2 - amax) : 0.0f;

    float s = e0 + e1 + e2;
    #pragma unroll
    for (int o = 16; o; o >>= 1)
        s += __shfl_xor_sync(0xffffffffu, s, o);

    const float recip = 1.0f / s;
    float o0 = e0 * recip, o1 = e1 * recip, o2 = e2 * recip;

    float* out = cls_out + (size_t)row * NCLS;
    out[lane]      = o0;
    out[lane + 32] = o1;
    if (has2) out[lane + 64] = o2;

    float m = fmaxf(o0, o1);
    if (has2) m = fmaxf(m, o2);
    #pragma unroll
    for (int o = 16; o; o >>= 1)
        m = fmaxf(m, __shfl_xor_sync(0xffffffffu, m, o));

    if (lane == 0) {
        const unsigned n = (unsigned)(row & (NBOX - 1));
        keys[row] = ((unsigned long long)__float_as_uint(m) << 32)
                  | (unsigned long long)(0xffffffffu - n);
    }
}

// ---------------------------------------------------------------------------
// Kernel 2: per-batch sort + NMS, everything in shared memory.
// Dynamic smem: float4 sbox[NBOX] | u64 sk[NBOX] | float sarea[NBOX]
// ---------------------------------------------------------------------------
__global__ void __launch_bounds__(1024)
nms_kernel(const float* __restrict__ boxes,        // [B,N,4]
           const float* __restrict__ cls_soft,     // [B,N,C]
           const unsigned long long* __restrict__ keys,
           float* __restrict__ nms_box,            // [B,MAX_DET,4]
           float* __restrict__ nms_cls)            // [B,MAX_DET,C]
{
    extern __shared__ char dyn[];
    float4*             sbox  = (float4*)dyn;                       // 64KB
    unsigned long long* sk    = (unsigned long long*)(sbox + NBOX); // 32KB
    float*              sarea = (float*)(sk + NBOX);                // 16KB

    __shared__ int kidx[MAX_DET];
    __shared__ int s_count;

    const int b    = blockIdx.x;
    const int tid  = threadIdx.x;
    const int lane = tid & 31;
    const int warp = tid >> 5;
    const int nwarps = blockDim.x >> 5;

    // ---- load keys + pre-normalized boxes into smem ----
    const float4* bb4 = (const float4*)(boxes + (size_t)b * NBOX * 4);
    for (int i = tid; i < NBOX; i += blockDim.x) {
        sk[i] = keys[b * NBOX + i];
        float4 r = bb4[i];
        float y1 = fminf(r.x, r.z), y2 = fmaxf(r.x, r.z);
        float x1 = fminf(r.y, r.w), x2 = fmaxf(r.y, r.w);
        sbox[i]  = make_float4(y1, x1, y2, x2);
        sarea[i] = (y2 - y1) * (x2 - x1);
    }
    __syncthreads();

    // ---- bitonic sort, descending; j>=32 in smem, j<=16 via warp shuffles ----
    for (int k = 2; k <= NBOX; k <<= 1) {
        for (int j = k >> 1; j >= 32; j >>= 1) {
            for (int p = tid; p < NBOX / 2; p += blockDim.x) {
                int i = ((p & ~(j - 1)) << 1) | (p & (j - 1));
                int l = i | j;
                unsigned long long a = sk[i], c = sk[l];
                bool sw = ((i & k) == 0) ? (a < c) : (a > c);
                if (sw) { sk[i] = c; sk[l] = a; }
            }
            __syncthreads();
        }
        const int jstart = (k >> 1) < 16 ? (k >> 1) : 16;
        for (int seg = warp; seg < NBOX / 32; seg += nwarps) {
            const int i = (seg << 5) + lane;
            unsigned long long v = sk[i];
            const bool desc = ((i & k) == 0);
            for (int j = jstart; j >= 1; j >>= 1) {
                unsigned long long w = __shfl_xor_sync(0xffffffffu, v, j);
                bool upper   = (i & j) != 0;
                bool takeMax = desc ^ upper;
                v = takeMax ? (v > w ? v : w) : (v < w ? v : w);
            }
            sk[i] = v;
        }
        __syncthreads();
    }

    // ---- greedy NMS (warp 0 only); kept boxes live in registers:
    //      lane L owns kept slots L, L+32, L+64, L+96 ----
    if (warp == 0) {
        float4 kb0, kb1, kb2, kb3;          // y1,x1,y2,x2 of owned kept boxes
        float  ka0 = 0.f, ka1 = 0.f, ka2 = 0.f, ka3 = 0.f;
        int count = 0;

        for (int r = 0; r < NBOX && count < MAX_DET; r++) {
            const unsigned long long key = sk[r];
            const float score = __uint_as_float((unsigned)(key >> 32));
            if (!(score > CONF_THR)) break;
            const int idx = (int)(0xffffffffu - (unsigned)(key & 0xffffffffu));

            const float4 c  = sbox[idx];     // uniform -> smem broadcast
            const float  ca = sarea[idx];

            bool sup = false;
            {
                if (lane < count) {
                    float ih = fmaxf(0.0f, fminf(c.z, kb0.z) - fmaxf(c.x, kb0.x));
                    float iw = fmaxf(0.0f, fminf(c.w, kb0.w) - fmaxf(c.y, kb0.y));
                    float inter = ih * iw;
                    float iou = (inter > 0.0f) ? inter / (ca + ka0 - inter) : 0.0f;
                    sup |= (iou > IOU_THR);
                }
                if (lane + 32 < count) {
                    float ih = fmaxf(0.0f, fminf(c.z, kb1.z) - fmaxf(c.x, kb1.x));
                    float iw = fmaxf(0.0f, fminf(c.w, kb1.w) - fmaxf(c.y, kb1.y));
                    float inter = ih * iw;
                    float iou = (inter > 0.0f) ? inter / (ca + ka1 - inter) : 0.0f;
                    sup |= (iou > IOU_THR);
                }
                if (lane + 64 < count) {
                    float ih = fmaxf(0.0f, fminf(c.z, kb2.z) - fmaxf(c.x, kb2.x));
                    float iw = fmaxf(0.0f, fminf(c.w, kb2.w) - fmaxf(c.y, kb2.y));
                    float inter = ih * iw;
                    float iou = (inter > 0.0f) ? inter / (ca + ka2 - inter) : 0.0f;
                    sup |= (iou > IOU_THR);
                }
                if (lane + 96 < count) {
                    float ih = fmaxf(0.0f, fminf(c.z, kb3.z) - fmaxf(c.x, kb3.x));
                    float iw = fmaxf(0.0f, fminf(c.w, kb3.w) - fmaxf(c.y, kb3.y));
                    float inter = ih * iw;
                    float iou = (inter > 0.0f) ? inter / (ca + ka3 - inter) : 0.0f;
                    sup |= (iou > IOU_THR);
                }
            }
            if (__ballot_sync(0xffffffffu, sup) == 0u) {   // keep
                const int slot  = count >> 5;
                if (lane == (count & 31)) {
                    if      (slot == 0) { kb0 = c; ka0 = ca; }
                    else if (slot == 1) { kb1 = c; ka1 = ca; }
                    else if (slot == 2) { kb2 = c; ka2 = ca; }
                    else                { kb3 = c; ka3 = ca; }
                }
                if (lane == 0) kidx[count] = idx;
                count++;
            }
        }
        if (lane == 0) s_count = count;
    }
    __syncthreads();
    const int count = s_count;

    // ---- outputs (zero-pad beyond count) ----
    float* ob = nms_box + (size_t)b * MAX_DET * 4;
    for (int t = tid; t < MAX_DET * 4; t += blockDim.x) {
        int k = t >> 2, c = t & 3;
        ob[t] = (k < count)
              ? boxes[(size_t)b * NBOX * 4 + (size_t)kidx[k] * 4 + c]
              : 0.0f;
    }
    float* oc = nms_cls + (size_t)b * MAX_DET * NCLS;
    for (int t = tid; t < MAX_DET * NCLS; t += blockDim.x) {
        int k = t / NCLS, c = t % NCLS;
        oc[t] = (k < count)
              ? cls_soft[((size_t)b * NBOX + (size_t)kidx[k]) * NCLS + c]
              : 0.0f;
    }
}

// ---------------------------------------------------------------------------
extern "C" void kernel_launch(void* const* d_in, const int* in_sizes, int n_in,
                              void* d_out, int out_size)
{
    const float* boxes;
    const float* cls;
    if (in_sizes[0] == BATCH * NBOX * 4) {
        boxes = (const float*)d_in[0];
        cls   = (const float*)d_in[1];
    } else {
        boxes = (const float*)d_in[1];
        cls   = (const float*)d_in[0];
    }

    float* out      = (float*)d_out;
    float* nms_box  = out;                                  // [16,100,4]
    float* nms_cls  = out + BATCH * MAX_DET * 4;            // [16,100,80]
    float* cls_pred = out + BATCH * MAX_DET * 4
                          + BATCH * MAX_DET * NCLS;         // [16,4096,80]

    unsigned long long* keys = nullptr;
    cudaGetSymbolAddress((void**)&keys, g_keys);

    const int DYN_SMEM = NBOX * (int)sizeof(float4)
                       + NBOX * (int)sizeof(unsigned long long)
                       + NBOX * (int)sizeof(float);         // 112 KB
    static int smem_set = 0;
    if (!smem_set) {
        cudaFuncSetAttribute(nms_kernel,
                             cudaFuncAttributeMaxDynamicSharedMemorySize,
                             DYN_SMEM);
        smem_set = 1;
    }

    const int rows = BATCH * NBOX;
    softmax_key_kernel<<<rows / 8, 256>>>(cls, cls_pred, keys);
    nms_kernel<<<BATCH, 1024, DYN_SMEM>>>(boxes, cls_pred, keys, nms_box, nms_cls);
}

// round 3
// speedup vs baseline: 1.5060x; 1.0773x over previous
#include <cuda_runtime.h>
#include <stdint.h>

#define BATCH    16
#define NBOX     4096
#define NCLS     80
#define MAX_DET  100
#define IOU_THR  0.5f
#define CONF_THR 0.5f
#define FULL     0xffffffffu

// scratch: per-row sort keys  (score_bits << 32) | (0xFFFFFFFF - idx)
__device__ unsigned long long g_keys[BATCH * NBOX];

// ---------------------------------------------------------------------------
// Kernel 1: softmax(square(x*10)) per row, write cls_predictions, emit keys.
// One warp per row of 80.
// ---------------------------------------------------------------------------
__global__ void __launch_bounds__(256)
softmax_key_kernel(const float* __restrict__ cls_in,
                   float* __restrict__ cls_out,
                   unsigned long long* __restrict__ keys)
{
    const int lane = threadIdx.x & 31;
    const int row  = blockIdx.x * (blockDim.x >> 5) + (threadIdx.x >> 5);
    if (row >= BATCH * NBOX) return;

    const float* in = cls_in + (size_t)row * NCLS;

    const bool has2 = lane < (NCLS - 64);
    float x0 = in[lane]      * 10.0f;
    float x1 = in[lane + 32] * 10.0f;
    float x2 = has2 ? in[lane + 64] * 10.0f : 0.0f;
    float a0 = x0 * x0, a1 = x1 * x1, a2 = x2 * x2;

    float amax = fmaxf(a0, a1);
    if (has2) amax = fmaxf(amax, a2);
    #pragma unroll
    for (int o = 16; o; o >>= 1)
        amax = fmaxf(amax, __shfl_xor_sync(FULL, amax, o));

    float e0 = expf(a0 - amax);
    float e1 = expf(a1 - amax);
    float e2 = has2 ? expf(a2 - amax) : 0.0f;

    float s = e0 + e1 + e2;
    #pragma unroll
    for (int o = 16; o; o >>= 1)
        s += __shfl_xor_sync(FULL, s, o);

    const float recip = 1.0f / s;
    float o0 = e0 * recip, o1 = e1 * recip, o2 = e2 * recip;

    float* out = cls_out + (size_t)row * NCLS;
    out[lane]      = o0;
    out[lane + 32] = o1;
    if (has2) out[lane + 64] = o2;

    float m = fmaxf(o0, o1);
    if (has2) m = fmaxf(m, o2);
    #pragma unroll
    for (int o = 16; o; o >>= 1)
        m = fmaxf(m, __shfl_xor_sync(FULL, m, o));

    if (lane == 0) {
        const unsigned n = (unsigned)(row & (NBOX - 1));
        keys[row] = ((unsigned long long)__float_as_uint(m) << 32)
                  | (unsigned long long)(0xffffffffu - n);
    }
}

// ---------------------------------------------------------------------------
// Kernel 2: per-batch sort + chunked-warp NMS, everything in shared memory.
// Dynamic smem: float4 sbox[NBOX] | u64 sk[NBOX] | float sarea[NBOX]
// ---------------------------------------------------------------------------
__global__ void __launch_bounds__(1024)
nms_kernel(const float* __restrict__ boxes,        // [B,N,4]
           const float* __restrict__ cls_soft,     // [B,N,C]
           const unsigned long long* __restrict__ keys,
           float* __restrict__ nms_box,            // [B,MAX_DET,4]
           float* __restrict__ nms_cls)            // [B,MAX_DET,C]
{
    extern __shared__ char dyn[];
    float4*             sbox  = (float4*)dyn;                       // 64KB
    unsigned long long* sk    = (unsigned long long*)(sbox + NBOX); // 32KB
    float*              sarea = (float*)(sk + NBOX);                // 16KB

    __shared__ float ky1[MAX_DET], kx1[MAX_DET], ky2[MAX_DET], kx2[MAX_DET], kar[MAX_DET];
    __shared__ int   kidx[MAX_DET];
    __shared__ int   s_count;

    const int b    = blockIdx.x;
    const int tid  = threadIdx.x;
    const int lane = tid & 31;
    const int warp = tid >> 5;
    const int nwarps = blockDim.x >> 5;

    // ---- load keys + pre-normalized boxes into smem ----
    const float4* bb4 = (const float4*)(boxes + (size_t)b * NBOX * 4);
    for (int i = tid; i < NBOX; i += blockDim.x) {
        sk[i] = keys[b * NBOX + i];
        float4 r = bb4[i];
        float y1 = fminf(r.x, r.z), y2 = fmaxf(r.x, r.z);
        float x1 = fminf(r.y, r.w), x2 = fmaxf(r.y, r.w);
        sbox[i]  = make_float4(y1, x1, y2, x2);
        sarea[i] = (y2 - y1) * (x2 - x1);
    }
    __syncthreads();

    // ---- bitonic sort, descending ----
    // stage A: all k<=32 fused, pure warp shuffles, one smem round-trip
    for (int seg = warp; seg < NBOX / 32; seg += nwarps) {
        const int i = (seg << 5) + lane;
        unsigned long long v = sk[i];
        #pragma unroll
        for (int k = 2; k <= 32; k <<= 1) {
            const bool desc = ((i & k) == 0);
            #pragma unroll
            for (int j = k >> 1; j >= 1; j >>= 1) {
                unsigned long long w = __shfl_xor_sync(FULL, v, j);
                bool upper   = (i & j) != 0;
                bool takeMax = desc ^ upper;
                v = takeMax ? (v > w ? v : w) : (v < w ? v : w);
            }
        }
        sk[i] = v;
    }
    __syncthreads();

    // stage B: k>=64; j>=32 via smem, j<=16 via shuffles
    for (int k = 64; k <= NBOX; k <<= 1) {
        for (int j = k >> 1; j >= 32; j >>= 1) {
            for (int p = tid; p < NBOX / 2; p += blockDim.x) {
                int i = ((p & ~(j - 1)) << 1) | (p & (j - 1));
                int l = i | j;
                unsigned long long a = sk[i], c = sk[l];
                bool sw = ((i & k) == 0) ? (a < c) : (a > c);
                if (sw) { sk[i] = c; sk[l] = a; }
            }
            __syncthreads();
        }
        for (int seg = warp; seg < NBOX / 32; seg += nwarps) {
            const int i = (seg << 5) + lane;
            unsigned long long v = sk[i];
            const bool desc = ((i & k) == 0);
            #pragma unroll
            for (int j = 16; j >= 1; j >>= 1) {
                unsigned long long w = __shfl_xor_sync(FULL, v, j);
                bool upper   = (i & j) != 0;
                bool takeMax = desc ^ upper;
                v = takeMax ? (v > w ? v : w) : (v < w ? v : w);
            }
            sk[i] = v;
        }
        __syncthreads();
    }

    // ---- chunked greedy NMS (warp 0): 32 candidates per chunk ----
    if (warp == 0) {
        int count = 0;
        for (int r = 0; r < NBOX; r += 32) {
            const unsigned long long key = sk[r + lane];
            const float score = __uint_as_float((unsigned)(key >> 32));
            const bool  valid = score > CONF_THR;
            const unsigned vmask = __ballot_sync(FULL, valid);
            if (vmask == 0) break;

            const int idx = (int)(0xffffffffu - (unsigned)(key & 0xffffffffu));
            float4 c  = make_float4(0.f, 0.f, 0.f, 0.f);
            float  ca = 0.f;
            if (valid) { c = sbox[idx]; ca = sarea[idx]; }

            // check my candidate vs all previously-kept boxes (parallel over lanes)
            bool aliveL = valid;
            for (int j = 0; j < count && aliveL; j++) {
                float ih = fmaxf(0.0f, fminf(c.z, ky2[j]) - fmaxf(c.x, ky1[j]));
                float iw = fmaxf(0.0f, fminf(c.w, kx2[j]) - fmaxf(c.y, kx1[j]));
                float inter = ih * iw;
                float iou = (inter > 0.0f) ? inter / (ca + kar[j] - inter) : 0.0f;
                if (iou > IOU_THR) aliveL = false;
            }

            // serial intra-chunk resolve: only per-KEEP work is serialized
            unsigned alive = __ballot_sync(FULL, aliveL);
            while (alive && count < MAX_DET) {
                const int i = __ffs(alive) - 1;
                const float y1 = __shfl_sync(FULL, c.x, i);
                const float x1 = __shfl_sync(FULL, c.y, i);
                const float y2 = __shfl_sync(FULL, c.z, i);
                const float x2 = __shfl_sync(FULL, c.w, i);
                const float a  = __shfl_sync(FULL, ca,  i);
                const int   ki = __shfl_sync(FULL, idx, i);
                if (lane == 0) {
                    ky1[count] = y1; kx1[count] = x1;
                    ky2[count] = y2; kx2[count] = x2;
                    kar[count] = a;  kidx[count] = ki;
                }
                count++;
                if (aliveL) {
                    if (lane == i) aliveL = false;
                    else {
                        float ih = fmaxf(0.0f, fminf(c.z, y2) - fmaxf(c.x, y1));
                        float iw = fmaxf(0.0f, fminf(c.w, x2) - fmaxf(c.y, x1));
                        float inter = ih * iw;
                        float iou = (inter > 0.0f) ? inter / (ca + a - inter) : 0.0f;
                        if (iou > IOU_THR) aliveL = false;
                    }
                }
                alive = __ballot_sync(FULL, aliveL);
            }
            __syncwarp();   // kept-array writes visible to next chunk's reads

            if (count >= MAX_DET) break;
            if (vmask != FULL) break;   // invalid tail started: rest is invalid
        }
        if (lane == 0) s_count = count;
    }
    __syncthreads();
    const int count = s_count;

    // ---- outputs (zero-pad beyond count) ----
    float* ob = nms_box + (size_t)b * MAX_DET * 4;
    for (int t = tid; t < MAX_DET * 4; t += blockDim.x) {
        int k = t >> 2, c = t & 3;
        ob[t] = (k < count)
              ? boxes[(size_t)b * NBOX * 4 + (size_t)kidx[k] * 4 + c]
              : 0.0f;
    }
    float* oc = nms_cls + (size_t)b * MAX_DET * NCLS;
    for (int t = tid; t < MAX_DET * NCLS; t += blockDim.x) {
        int k = t / NCLS, c = t % NCLS;
        oc[t] = (k < count)
              ? cls_soft[((size_t)b * NBOX + (size_t)kidx[k]) * NCLS + c]
              : 0.0f;
    }
}

// ---------------------------------------------------------------------------
extern "C" void kernel_launch(void* const* d_in, const int* in_sizes, int n_in,
                              void* d_out, int out_size)
{
    const float* boxes;
    const float* cls;
    if (in_sizes[0] == BATCH * NBOX * 4) {
        boxes = (const float*)d_in[0];
        cls   = (const float*)d_in[1];
    } else {
        boxes = (const float*)d_in[1];
        cls   = (const float*)d_in[0];
    }

    float* out      = (float*)d_out;
    float* nms_box  = out;                                  // [16,100,4]
    float* nms_cls  = out + BATCH * MAX_DET * 4;            // [16,100,80]
    float* cls_pred = out + BATCH * MAX_DET * 4
                          + BATCH * MAX_DET * NCLS;         // [16,4096,80]

    unsigned long long* keys = nullptr;
    cudaGetSymbolAddress((void**)&keys, g_keys);

    const int DYN_SMEM = NBOX * (int)sizeof(float4)
                       + NBOX * (int)sizeof(unsigned long long)
                       + NBOX * (int)sizeof(float);         // 112 KB
    static int smem_set = 0;
    if (!smem_set) {
        cudaFuncSetAttribute(nms_kernel,
                             cudaFuncAttributeMaxDynamicSharedMemorySize,
                             DYN_SMEM);
        smem_set = 1;
    }

    const int rows = BATCH * NBOX;
    softmax_key_kernel<<<rows / 8, 256>>>(cls, cls_pred, keys);
    nms_kernel<<<BATCH, 1024, DYN_SMEM>>>(boxes, cls_pred, keys, nms_box, nms_cls);
}